// round 10
// baseline (speedup 1.0000x reference)
#include <cuda_runtime.h>
#include <cuda_fp16.h>
#include <math.h>
#include <stdint.h>

#define D 64
#define NNODES 512
#define NTOT 4096
#define HDIM 192
#define EMAX 131072
#define NWARP 16
#define THREADS (NWARP * 32)
#define ROWB 144
#define F32RB 272

// ---- smem layout (bytes) ----
#define OFF_W   0                        // [192][72] fp16 rows (144B) = 27648
#define OFF_W2  27648                    // 192 f32 = 768
#define OFF_A   28416                    // 16 warps x 6912
#define AWARP   6912                     //  fp16 rows [16][144]=2304 ; f32 rows [16][272]=4352 @+2304
#define OFF_SS  139008                   // 16w x 16 int = 1024
#define OFF_SD  140032
#define OFF_AT  141056
#define SMEM_TOTAL 142080

__device__ float  g_denom[NTOT];
__device__ __half g_PdH[NTOT * HDIM];   // fp16 P: nf @ W1[:,0:64]^T
__device__ __half g_PsH[NTOT * HDIM];   // fp16 P: nf @ W1[:,64:128]^T
__device__ int    g_is64;

__device__ __forceinline__ long long ldidx(const void* ei, int i, int is64) {
    return is64 ? ((const long long*)ei)[i] : (long long)((const int*)ei)[i];
}
__device__ __forceinline__ void ldsm4(uint32_t* r, uint32_t a) {
    asm volatile("ldmatrix.sync.aligned.m8n8.x4.shared.b16 {%0,%1,%2,%3}, [%4];"
                 : "=r"(r[0]), "=r"(r[1]), "=r"(r[2]), "=r"(r[3]) : "r"(a));
}
__device__ __forceinline__ void mma_fp16(float* c, const uint32_t* a, const uint32_t* b) {
    asm volatile("mma.sync.aligned.m16n8k16.row.col.f32.f16.f16.f32 "
                 "{%0,%1,%2,%3}, {%4,%5,%6,%7}, {%8,%9}, {%0,%1,%2,%3};"
                 : "+f"(c[0]), "+f"(c[1]), "+f"(c[2]), "+f"(c[3])
                 : "r"(a[0]), "r"(a[1]), "r"(a[2]), "r"(a[3]), "r"(b[0]), "r"(b[1]));
}
__device__ __forceinline__ void red4(float* p, float a, float b, float c, float d) {
    asm volatile("red.global.add.v4.f32 [%0], {%1,%2,%3,%4};"
                 :: "l"(p), "f"(a), "f"(b), "f"(c), "f"(d) : "memory");
}
__device__ __forceinline__ uint2 pack_h4(float4 v) {
    __half2 p0 = __floats2half2_rn(v.x, v.y);
    __half2 p1 = __floats2half2_rn(v.z, v.w);
    uint2 u;
    u.x = *reinterpret_cast<uint32_t*>(&p0);
    u.y = *reinterpret_cast<uint32_t*>(&p1);
    return u;
}
__device__ __forceinline__ float gelu_x(float x) {
    return 0.5f * x * (1.0f + erff(x * 0.70710678118654752f));
}

// Fused: zero out/denom + int-width detect + P precompute.
// 256 blocks: 128 node-tiles (32 nodes) x 2 halves. fp32 compute, fp16 store.
__global__ __launch_bounds__(256, 3) void precompute_kernel(
    const float* __restrict__ nf, const float* __restrict__ W1,
    const void* __restrict__ ei, float* __restrict__ out)
{
    extern __shared__ float psm[];
    float* Ws = psm;                // [64][192]: Ws[k*192+o] = W1[o][base+k]
    float* Ns = psm + 64 * HDIM;    // [32][64]

    int half = blockIdx.x & 1;
    int tile = blockIdx.x >> 1;
    int tid = threadIdx.x, lane = tid & 31, warp = tid >> 5;
    __half* P = half ? g_PsH : g_PdH;

    // zero out + denom (256 blocks x 256 float4 = NTOT*D floats)
    ((float4*)out)[blockIdx.x * 256 + tid] = make_float4(0.f, 0.f, 0.f, 0.f);
    if (tid < 16) g_denom[blockIdx.x * 16 + tid] = 0.0f;
    // int64 vs int32 detect (block 0; range-probe 256 int64 words)
    if (blockIdx.x == 0) {
        const long long* p = (const long long*)ei;
        long long v = p[tid];
        int ok = (v >= 0 && v < NTOT);
        int all = __syncthreads_and(ok);
        if (tid == 0) g_is64 = all;
    }

    // Stage Ws transposed: float4 loads of W1[o][base .. base+63]
    for (int i = tid; i < HDIM * 16; i += 256) {
        int o = i >> 4, r = i & 15;
        float4 v = *(const float4*)(W1 + o * HDIM + 64 * half + r * 4);
        Ws[(r * 4 + 0) * HDIM + o] = v.x;
        Ws[(r * 4 + 1) * HDIM + o] = v.y;
        Ws[(r * 4 + 2) * HDIM + o] = v.z;
        Ws[(r * 4 + 3) * HDIM + o] = v.w;
    }
    for (int i = tid; i < 32 * 64 / 4; i += 256)
        ((float4*)Ns)[i] = ((const float4*)(nf + tile * 32 * D))[i];
    __syncthreads();

    float acc[4][6];
    #pragma unroll
    for (int e = 0; e < 4; ++e)
        #pragma unroll
        for (int j = 0; j < 6; ++j) acc[e][j] = 0.0f;

    const float* hb = Ns + (warp * 4) * 64;
    #pragma unroll 4
    for (int k = 0; k < 64; ++k) {
        const float* w = Ws + k * HDIM + lane;
        float wv[6];
        #pragma unroll
        for (int j = 0; j < 6; ++j) wv[j] = w[32 * j];
        #pragma unroll
        for (int e = 0; e < 4; ++e) {
            float hv = hb[e * 64 + k];
            #pragma unroll
            for (int j = 0; j < 6; ++j) acc[e][j] = fmaf(hv, wv[j], acc[e][j]);
        }
    }
    int nbase = tile * 32 + warp * 4;
    #pragma unroll
    for (int e = 0; e < 4; ++e)
        #pragma unroll
        for (int j = 0; j < 6; ++j)
            P[(nbase + e) * HDIM + lane + 32 * j] = __float2half(acc[e][j]);
}

// Warp-autonomous fused kernel: 16-edge warp tiles, single fp16 MMA, acc
// zero-init (P folded into the gelu epilogue to decouple L2 latency from
// the MMA chain). Exact fp32 edge rows kept in smem for output accumulate.
__global__ __launch_bounds__(THREADS, 1) void score_kernel(
    const float* __restrict__ adj, const float* __restrict__ W1,
    const float* __restrict__ W2, const void* __restrict__ ei,
    float* __restrict__ out, int E, int nwt)
{
    extern __shared__ __align__(16) char sm[];
    uint32_t smb = (uint32_t)__cvta_generic_to_shared(sm);
    float* W2s = (float*)(sm + OFF_W2);

    int tid = threadIdx.x, lane = tid & 31, wid = tid >> 5;
    int is64 = g_is64;

    // Stage W1c (cols 128..191) as fp16, rows = output o, K-major, 144B rows
    for (int i = tid; i < HDIM * 16; i += THREADS) {
        int o = i >> 4, r = i & 15;
        float4 v = *(const float4*)(W1 + o * HDIM + 128 + r * 4);
        *(uint2*)(sm + OFF_W + o * ROWB + r * 8) = pack_h4(v);
    }
    for (int i = tid; i < HDIM; i += THREADS) W2s[i] = W2[i];
    __syncthreads();

    char* Ah  = sm + OFF_A + wid * AWARP;       // fp16 rows [16][144]
    char* F32 = Ah + 2304;                      // fp32 rows [16][272]
    uint32_t ah_u = smb + OFF_A + wid * AWARP;
    uint32_t w_u  = smb + OFF_W;
    int*   sSw = (int*)(sm + OFF_SS) + wid * 16;
    int*   sDw = (int*)(sm + OFF_SD) + wid * 16;
    float* ATw = (float*)(sm + OFF_AT) + wid * 16;

    int gw = blockIdx.x * NWARP + wid;
    for (int wt = gw; wt < nwt; wt += gridDim.x * NWARP) {
        int tbase = wt * 16;
        // ---- stage indices ----
        if (lane < 16) {
            int ge = tbase + lane;
            int s = 0, d = 0;
            if (ge < E) {
                s = (int)ldidx(ei, ge, is64);
                d = (int)ldidx(ei, E + ge, is64);
            }
            sSw[lane] = s; sDw[lane] = d;
        }
        __syncwarp();
        // ---- gather adj rows: fp16 copy for MMA + fp32 copy for output ----
        {
            int r = lane >> 1, h = lane & 1;
            int ge = tbase + r;
            int s = sSw[r], d = sDw[r];
            const float4* rowp =
                (const float4*)(adj + ((long long)s * NNODES + (d & (NNODES - 1))) * D);
            #pragma unroll
            for (int j = 0; j < 8; ++j) {
                float4 v = (ge < E) ? rowp[h * 8 + j]
                                    : make_float4(0.f, 0.f, 0.f, 0.f);
                *(uint2*)(Ah + r * ROWB + (h * 8 + j) * 8) = pack_h4(v);
                *(float4*)(F32 + r * F32RB + (h * 8 + j) * 16) = v;
            }
        }
        __syncwarp();

        int r0 = lane >> 2, r1 = r0 + 8;
        int s0 = sSw[r0], d0 = sDw[r0], s1 = sSw[r1], d1 = sDw[r1];
        const __half2* pd0 = (const __half2*)(g_PdH + d0 * HDIM);
        const __half2* ps0 = (const __half2*)(g_PsH + s0 * HDIM);
        const __half2* pd1 = (const __half2*)(g_PdH + d1 * HDIM);
        const __half2* ps1 = (const __half2*)(g_PsH + s1 * HDIM);

        // A fragments are nc-invariant: hoist (4 kk x 4 regs)
        uint32_t ahf[4][4];
        #pragma unroll
        for (int kk = 0; kk < 4; ++kk) {
            uint32_t aoff = (uint32_t)((lane & 15) * ROWB + kk * 32 + (lane >> 4) * 16);
            ldsm4(ahf[kk], ah_u + aoff);
        }

        float z0 = 0.0f, z1 = 0.0f;
        #pragma unroll
        for (int nc = 0; nc < 3; ++nc) {
            float acc[8][4] = {};
            int cb = nc * 64;
            #pragma unroll
            for (int kk = 0; kk < 4; ++kk) {
                #pragma unroll
                for (int fp = 0; fp < 4; ++fp) {
                    // B frags for col groups f=2fp, 2fp+1 in one ldsm4
                    uint32_t wa = w_u + (uint32_t)((cb + fp * 16 + (lane & 7) + ((lane >> 4) << 3)) * ROWB
                                                   + kk * 32 + ((lane >> 3) & 1) * 16);
                    uint32_t bh[4];
                    ldsm4(bh, wa);
                    mma_fp16(acc[2 * fp],     ahf[kk], bh);
                    mma_fp16(acc[2 * fp + 1], ahf[kk], bh + 2);
                }
            }
            // epilogue: x = acc + Pd[dst] + Ps[src] (fp16 P), z += gelu(x)*W2
            #pragma unroll
            for (int f = 0; f < 8; ++f) {
                int c0 = cb + f * 8 + 2 * (lane & 3);   // even
                int ch = c0 >> 1;
                float2 a0 = __half22float2(pd0[ch]);
                float2 b0 = __half22float2(ps0[ch]);
                float2 a1 = __half22float2(pd1[ch]);
                float2 b1 = __half22float2(ps1[ch]);
                float2 w2v = *(const float2*)(W2s + c0);
                z0 = fmaf(gelu_x(acc[f][0] + a0.x + b0.x), w2v.x, z0);
                z0 = fmaf(gelu_x(acc[f][1] + a0.y + b0.y), w2v.y, z0);
                z1 = fmaf(gelu_x(acc[f][2] + a1.x + b1.x), w2v.x, z1);
                z1 = fmaf(gelu_x(acc[f][3] + a1.y + b1.y), w2v.y, z1);
            }
        }
        // quad reduce (lanes sharing the same rows)
        z0 += __shfl_xor_sync(0xffffffffu, z0, 1);
        z0 += __shfl_xor_sync(0xffffffffu, z0, 2);
        z1 += __shfl_xor_sync(0xffffffffu, z1, 1);
        z1 += __shfl_xor_sync(0xffffffffu, z1, 2);

        if ((lane & 3) == 0) {
            int df0 = (s0 > d0 ? s0 - d0 : d0 - s0);
            int df1 = (s1 > d1 ? s1 - d1 : d1 - s1);
            float at0 = (tbase + r0 < E && df0 > 1) ? expf(z0) : 0.0f;
            float at1 = (tbase + r1 < E && df1 > 1) ? expf(z1) : 0.0f;
            ATw[r0] = at0; ATw[r1] = at1;
            if (at0 != 0.0f) atomicAdd(&g_denom[d0], at0);
            if (at1 != 0.0f) atomicAdd(&g_denom[d1], at1);
        }
        __syncwarp();

        // weighted accumulate from the exact fp32 rows: 2 edges/pass, red.v4
        #pragma unroll
        for (int ep = 0; ep < 8; ++ep) {
            int e = 2 * ep + (lane >> 4);
            float a = ATw[e];
            if (a != 0.0f) {
                int c4 = lane & 15;
                float4 v = *(const float4*)(F32 + e * F32RB + c4 * 16);
                red4(out + sDw[e] * D + c4 * 4, v.x * a, v.y * a, v.z * a, v.w * a);
            }
        }
        __syncwarp();
    }
}

__global__ void finalize_kernel(float* __restrict__ out) {
    int i = blockIdx.x * blockDim.x + threadIdx.x;   // 65536 threads, float4 each
    float dn = g_denom[i >> 4];
    float inv = 1.0f / (dn == 0.0f ? 1.0f : dn);
    float4 v = ((float4*)out)[i];
    v.x *= inv; v.y *= inv; v.z *= inv; v.w *= inv;
    ((float4*)out)[i] = v;
}

extern "C" void kernel_launch(void* const* d_in, const int* in_sizes, int n_in,
                              void* d_out, int out_size) {
    const float* nf  = (const float*)d_in[0];
    const float* adj = (const float*)d_in[1];
    const float* W1  = (const float*)d_in[2];
    const float* W2  = (const float*)d_in[3];
    const void*  ei  = d_in[4];
    int E = in_sizes[4] / 2;
    if (E > EMAX) E = EMAX;

    const int pre_smem = (64 * HDIM + 32 * 64) * sizeof(float);
    cudaFuncSetAttribute(precompute_kernel, cudaFuncAttributeMaxDynamicSharedMemorySize, pre_smem);
    cudaFuncSetAttribute(score_kernel, cudaFuncAttributeMaxDynamicSharedMemorySize, SMEM_TOTAL);

    precompute_kernel<<<(NTOT / 32) * 2, 256, pre_smem>>>(nf, W1, ei, (float*)d_out);

    int nwt = (E + 15) / 16;
    score_kernel<<<148, THREADS, SMEM_TOTAL>>>(adj, W1, W2, ei, (float*)d_out, E, nwt);

    finalize_kernel<<<256, 256>>>((float*)d_out);
}

// round 11
// speedup vs baseline: 1.5986x; 1.5986x over previous
#include <cuda_runtime.h>
#include <cuda_fp16.h>
#include <math.h>
#include <stdint.h>

#define D 64
#define NNODES 512
#define NTOT 4096
#define HDIM 192
#define WSS 193            // padded Ws stride (bank-conflict-free)
#define EMAX 131072
#define NWARP 16
#define THREADS (NWARP * 32)
#define ROWB 144
#define F32RB 272

// ---- smem layout (bytes) ----
#define OFF_W   0                        // [192][72] fp16 rows (144B) = 27648
#define OFF_W2  27648                    // 192 f32 = 768
#define OFF_A   28416                    // 16 warps x 6912
#define AWARP   6912                     //  fp16 rows [16][144]=2304 ; f32 rows [16][272]=4352 @+2304
#define OFF_SS  139008                   // 16w x 16 int = 1024
#define OFF_SD  140032
#define OFF_AT  141056
#define SMEM_TOTAL 142080

__device__ float  g_denom[NTOT];
__device__ __half g_PdH[NTOT * HDIM];   // fp16 P: nf @ W1[:,0:64]^T
__device__ __half g_PsH[NTOT * HDIM];   // fp16 P: nf @ W1[:,64:128]^T
__device__ int    g_is64;

__device__ __forceinline__ long long ldidx(const void* ei, int i, int is64) {
    return is64 ? ((const long long*)ei)[i] : (long long)((const int*)ei)[i];
}
__device__ __forceinline__ void ldsm4(uint32_t* r, uint32_t a) {
    asm volatile("ldmatrix.sync.aligned.m8n8.x4.shared.b16 {%0,%1,%2,%3}, [%4];"
                 : "=r"(r[0]), "=r"(r[1]), "=r"(r[2]), "=r"(r[3]) : "r"(a));
}
__device__ __forceinline__ void mma_fp16(float* c, const uint32_t* a, const uint32_t* b) {
    asm volatile("mma.sync.aligned.m16n8k16.row.col.f32.f16.f16.f32 "
                 "{%0,%1,%2,%3}, {%4,%5,%6,%7}, {%8,%9}, {%0,%1,%2,%3};"
                 : "+f"(c[0]), "+f"(c[1]), "+f"(c[2]), "+f"(c[3])
                 : "r"(a[0]), "r"(a[1]), "r"(a[2]), "r"(a[3]), "r"(b[0]), "r"(b[1]));
}
__device__ __forceinline__ void red4(float* p, float a, float b, float c, float d) {
    asm volatile("red.global.add.v4.f32 [%0], {%1,%2,%3,%4};"
                 :: "l"(p), "f"(a), "f"(b), "f"(c), "f"(d) : "memory");
}
__device__ __forceinline__ uint2 pack_h4(float4 v) {
    __half2 p0 = __floats2half2_rn(v.x, v.y);
    __half2 p1 = __floats2half2_rn(v.z, v.w);
    uint2 u;
    u.x = *reinterpret_cast<uint32_t*>(&p0);
    u.y = *reinterpret_cast<uint32_t*>(&p1);
    return u;
}
__device__ __forceinline__ float gelu_x(float x) {
    return 0.5f * x * (1.0f + erff(x * 0.70710678118654752f));
}

// Fused: zero out/denom (all 128 blocks), int-width detect (block 0),
// P[n][o] = sum_k nf[n][k]*W1[o][64*half+k] (fp32 compute, fp16 store).
// Ws stride padded to 193 floats: staging STS and compute LDS both
// bank-conflict-free (bank = (k + o|lane) mod 32).
__global__ __launch_bounds__(256, 2) void precompute_kernel(
    const float* __restrict__ nf, const float* __restrict__ W1,
    const void* __restrict__ ei, float* __restrict__ out)
{
    extern __shared__ float psm[];
    float* Ws = psm;                // [64][193]: Ws[k*193+o] = W1[o][base+k]
    float* Ns = psm + 64 * WSS;     // [64][64]

    int half = blockIdx.x & 1;
    int tile = blockIdx.x >> 1;
    int tid = threadIdx.x, lane = tid & 31, warp = tid >> 5;
    __half* P = half ? g_PsH : g_PdH;

    // zero out + denom (128 blocks cover NTOT*D floats; 512 float4 per block)
    {
        float4 z4 = make_float4(0.f, 0.f, 0.f, 0.f);
        ((float4*)out)[blockIdx.x * 512 + tid]       = z4;
        ((float4*)out)[blockIdx.x * 512 + 256 + tid] = z4;
        if (tid < 32) g_denom[blockIdx.x * 32 + tid] = 0.0f;
    }
    // int64 vs int32 detect (block 0; range-probe 256 int64 words)
    if (blockIdx.x == 0) {
        const long long* p = (const long long*)ei;
        long long v = p[tid];
        int ok = (v >= 0 && v < NTOT);
        int all = __syncthreads_and(ok);
        if (tid == 0) g_is64 = all;
    }

    for (int i = tid; i < HDIM * 64; i += 256) {
        int o = i >> 6, k = i & 63;
        Ws[k * WSS + o] = W1[o * HDIM + 64 * half + k];
    }
    for (int i = tid; i < 64 * 64 / 4; i += 256)
        ((float4*)Ns)[i] = ((const float4*)(nf + tile * 64 * D))[i];
    __syncthreads();

    float acc[8][6];
    #pragma unroll
    for (int e = 0; e < 8; ++e)
        #pragma unroll
        for (int j = 0; j < 6; ++j) acc[e][j] = 0.0f;

    const float* hb = Ns + (warp * 8) * 64;
    #pragma unroll 4
    for (int k = 0; k < 64; ++k) {
        const float* w = Ws + k * WSS + lane;
        float wv[6];
        #pragma unroll
        for (int j = 0; j < 6; ++j) wv[j] = w[32 * j];
        #pragma unroll
        for (int e = 0; e < 8; ++e) {
            float hv = hb[e * 64 + k];
            #pragma unroll
            for (int j = 0; j < 6; ++j) acc[e][j] = fmaf(hv, wv[j], acc[e][j]);
        }
    }
    int nbase = tile * 64 + warp * 8;
    #pragma unroll
    for (int e = 0; e < 8; ++e)
        #pragma unroll
        for (int j = 0; j < 6; ++j)
            P[(nbase + e) * HDIM + lane + 32 * j] = __float2half(acc[e][j]);
}

// Warp-autonomous fused kernel: 16-edge warp tiles, single fp16 MMA, acc
// zero-init (P folded into the gelu epilogue to decouple L2 latency from
// the MMA chain). Exact fp32 edge rows kept in smem for output accumulate.
__global__ __launch_bounds__(THREADS, 1) void score_kernel(
    const float* __restrict__ adj, const float* __restrict__ W1,
    const float* __restrict__ W2, const void* __restrict__ ei,
    float* __restrict__ out, int E, int nwt)
{
    extern __shared__ __align__(16) char sm[];
    uint32_t smb = (uint32_t)__cvta_generic_to_shared(sm);
    float* W2s = (float*)(sm + OFF_W2);

    int tid = threadIdx.x, lane = tid & 31, wid = tid >> 5;
    int is64 = g_is64;

    // Stage W1c (cols 128..191) as fp16, rows = output o, K-major, 144B rows
    for (int i = tid; i < HDIM * 16; i += THREADS) {
        int o = i >> 4, r = i & 15;
        float4 v = *(const float4*)(W1 + o * HDIM + 128 + r * 4);
        *(uint2*)(sm + OFF_W + o * ROWB + r * 8) = pack_h4(v);
    }
    for (int i = tid; i < HDIM; i += THREADS) W2s[i] = W2[i];
    __syncthreads();

    char* Ah  = sm + OFF_A + wid * AWARP;       // fp16 rows [16][144]
    char* F32 = Ah + 2304;                      // fp32 rows [16][272]
    uint32_t ah_u = smb + OFF_A + wid * AWARP;
    uint32_t w_u  = smb + OFF_W;
    int*   sSw = (int*)(sm + OFF_SS) + wid * 16;
    int*   sDw = (int*)(sm + OFF_SD) + wid * 16;
    float* ATw = (float*)(sm + OFF_AT) + wid * 16;

    int gw = blockIdx.x * NWARP + wid;
    for (int wt = gw; wt < nwt; wt += gridDim.x * NWARP) {
        int tbase = wt * 16;
        // ---- stage indices ----
        if (lane < 16) {
            int ge = tbase + lane;
            int s = 0, d = 0;
            if (ge < E) {
                s = (int)ldidx(ei, ge, is64);
                d = (int)ldidx(ei, E + ge, is64);
            }
            sSw[lane] = s; sDw[lane] = d;
        }
        __syncwarp();
        // ---- gather adj rows: fp16 copy for MMA + fp32 copy for output ----
        {
            int r = lane >> 1, h = lane & 1;
            int ge = tbase + r;
            int s = sSw[r], d = sDw[r];
            const float4* rowp =
                (const float4*)(adj + ((long long)s * NNODES + (d & (NNODES - 1))) * D);
            #pragma unroll
            for (int j = 0; j < 8; ++j) {
                float4 v = (ge < E) ? rowp[h * 8 + j]
                                    : make_float4(0.f, 0.f, 0.f, 0.f);
                *(uint2*)(Ah + r * ROWB + (h * 8 + j) * 8) = pack_h4(v);
                *(float4*)(F32 + r * F32RB + (h * 8 + j) * 16) = v;
            }
        }
        __syncwarp();

        int r0 = lane >> 2, r1 = r0 + 8;
        int s0 = sSw[r0], d0 = sDw[r0], s1 = sSw[r1], d1 = sDw[r1];
        const __half2* pd0 = (const __half2*)(g_PdH + d0 * HDIM);
        const __half2* ps0 = (const __half2*)(g_PsH + s0 * HDIM);
        const __half2* pd1 = (const __half2*)(g_PdH + d1 * HDIM);
        const __half2* ps1 = (const __half2*)(g_PsH + s1 * HDIM);

        // A fragments are nc-invariant: hoist (4 kk x 4 regs)
        uint32_t ahf[4][4];
        #pragma unroll
        for (int kk = 0; kk < 4; ++kk) {
            uint32_t aoff = (uint32_t)((lane & 15) * ROWB + kk * 32 + (lane >> 4) * 16);
            ldsm4(ahf[kk], ah_u + aoff);
        }

        float z0 = 0.0f, z1 = 0.0f;
        #pragma unroll
        for (int nc = 0; nc < 3; ++nc) {
            float acc[8][4] = {};
            int cb = nc * 64;
            #pragma unroll
            for (int kk = 0; kk < 4; ++kk) {
                #pragma unroll
                for (int fp = 0; fp < 4; ++fp) {
                    // B frags for col groups f=2fp, 2fp+1 in one ldsm4
                    uint32_t wa = w_u + (uint32_t)((cb + fp * 16 + (lane & 7) + ((lane >> 4) << 3)) * ROWB
                                                   + kk * 32 + ((lane >> 3) & 1) * 16);
                    uint32_t bh[4];
                    ldsm4(bh, wa);
                    mma_fp16(acc[2 * fp],     ahf[kk], bh);
                    mma_fp16(acc[2 * fp + 1], ahf[kk], bh + 2);
                }
            }
            // epilogue: x = acc + Pd[dst] + Ps[src] (fp16 P), z += gelu(x)*W2
            #pragma unroll
            for (int f = 0; f < 8; ++f) {
                int c0 = cb + f * 8 + 2 * (lane & 3);   // even
                int ch = c0 >> 1;
                float2 a0 = __half22float2(pd0[ch]);
                float2 b0 = __half22float2(ps0[ch]);
                float2 a1 = __half22float2(pd1[ch]);
                float2 b1 = __half22float2(ps1[ch]);
                float2 w2v = *(const float2*)(W2s + c0);
                z0 = fmaf(gelu_x(acc[f][0] + a0.x + b0.x), w2v.x, z0);
                z0 = fmaf(gelu_x(acc[f][1] + a0.y + b0.y), w2v.y, z0);
                z1 = fmaf(gelu_x(acc[f][2] + a1.x + b1.x), w2v.x, z1);
                z1 = fmaf(gelu_x(acc[f][3] + a1.y + b1.y), w2v.y, z1);
            }
        }
        // quad reduce (lanes sharing the same rows)
        z0 += __shfl_xor_sync(0xffffffffu, z0, 1);
        z0 += __shfl_xor_sync(0xffffffffu, z0, 2);
        z1 += __shfl_xor_sync(0xffffffffu, z1, 1);
        z1 += __shfl_xor_sync(0xffffffffu, z1, 2);

        if ((lane & 3) == 0) {
            int df0 = (s0 > d0 ? s0 - d0 : d0 - s0);
            int df1 = (s1 > d1 ? s1 - d1 : d1 - s1);
            float at0 = (tbase + r0 < E && df0 > 1) ? expf(z0) : 0.0f;
            float at1 = (tbase + r1 < E && df1 > 1) ? expf(z1) : 0.0f;
            ATw[r0] = at0; ATw[r1] = at1;
            if (at0 != 0.0f) atomicAdd(&g_denom[d0], at0);
            if (at1 != 0.0f) atomicAdd(&g_denom[d1], at1);
        }
        __syncwarp();

        // weighted accumulate from the exact fp32 rows: 2 edges/pass, red.v4
        #pragma unroll
        for (int ep = 0; ep < 8; ++ep) {
            int e = 2 * ep + (lane >> 4);
            float a = ATw[e];
            if (a != 0.0f) {
                int c4 = lane & 15;
                float4 v = *(const float4*)(F32 + e * F32RB + c4 * 16);
                red4(out + sDw[e] * D + c4 * 4, v.x * a, v.y * a, v.z * a, v.w * a);
            }
        }
        __syncwarp();
    }
}

__global__ void finalize_kernel(float* __restrict__ out) {
    int i = blockIdx.x * blockDim.x + threadIdx.x;   // 65536 threads, float4 each
    float dn = g_denom[i >> 4];
    float inv = 1.0f / (dn == 0.0f ? 1.0f : dn);
    float4 v = ((float4*)out)[i];
    v.x *= inv; v.y *= inv; v.z *= inv; v.w *= inv;
    ((float4*)out)[i] = v;
}

extern "C" void kernel_launch(void* const* d_in, const int* in_sizes, int n_in,
                              void* d_out, int out_size) {
    const float* nf  = (const float*)d_in[0];
    const float* adj = (const float*)d_in[1];
    const float* W1  = (const float*)d_in[2];
    const float* W2  = (const float*)d_in[3];
    const void*  ei  = d_in[4];
    int E = in_sizes[4] / 2;
    if (E > EMAX) E = EMAX;

    const int pre_smem = (64 * WSS + 64 * 64) * sizeof(float);
    cudaFuncSetAttribute(precompute_kernel, cudaFuncAttributeMaxDynamicSharedMemorySize, pre_smem);
    cudaFuncSetAttribute(score_kernel, cudaFuncAttributeMaxDynamicSharedMemorySize, SMEM_TOTAL);

    precompute_kernel<<<(NTOT / 64) * 2, 256, pre_smem>>>(nf, W1, ei, (float*)d_out);

    int nwt = (E + 15) / 16;
    score_kernel<<<148, THREADS, SMEM_TOTAL>>>(adj, W1, W2, ei, (float*)d_out, E, nwt);

    finalize_kernel<<<256, 256>>>((float*)d_out);
}

// round 12
// speedup vs baseline: 1.6656x; 1.0419x over previous
#include <cuda_runtime.h>
#include <cuda_fp16.h>
#include <math.h>
#include <stdint.h>

#define D 64
#define NNODES 512
#define NTOT 4096
#define HDIM 192
#define EMAX 131072
#define NWARP 16
#define THREADS (NWARP * 32)
#define ROWB 144
#define F32RB 272

// ---- score kernel smem layout (bytes) ----
#define OFF_W   0                        // [192][72] fp16 rows (144B) = 27648
#define OFF_W2  27648                    // 192 f32 = 768
#define OFF_A   28416                    // 16 warps x 6912
#define AWARP   6912                     //  fp16 rows [16][144]=2304 ; f32 rows [16][272]=4352 @+2304
#define OFF_SS  139008                   // 16w x 16 int = 1024
#define OFF_SD  140032
#define OFF_AT  141056
#define SMEM_TOTAL 142080

// ---- precompute kernel smem layout ----
#define POFF_WA 0                        // [192][72] fp16 rows, W1[:,0:64]
#define POFF_WB 27648                    // [192][72] fp16 rows, W1[:,64:128]
#define POFF_NF 55296                    // 16 warps x [16][144] fp16 = 36864
#define PSMEM_TOTAL 92160

__device__ float  g_denom[NTOT];
__device__ __half g_PdH[NTOT * HDIM];   // fp16 P: nf @ W1[:,0:64]^T
__device__ __half g_PsH[NTOT * HDIM];   // fp16 P: nf @ W1[:,64:128]^T
__device__ int    g_is64;

__device__ __forceinline__ long long ldidx(const void* ei, int i, int is64) {
    return is64 ? ((const long long*)ei)[i] : (long long)((const int*)ei)[i];
}
__device__ __forceinline__ void ldsm4(uint32_t* r, uint32_t a) {
    asm volatile("ldmatrix.sync.aligned.m8n8.x4.shared.b16 {%0,%1,%2,%3}, [%4];"
                 : "=r"(r[0]), "=r"(r[1]), "=r"(r[2]), "=r"(r[3]) : "r"(a));
}
__device__ __forceinline__ void mma_fp16(float* c, const uint32_t* a, const uint32_t* b) {
    asm volatile("mma.sync.aligned.m16n8k16.row.col.f32.f16.f16.f32 "
                 "{%0,%1,%2,%3}, {%4,%5,%6,%7}, {%8,%9}, {%0,%1,%2,%3};"
                 : "+f"(c[0]), "+f"(c[1]), "+f"(c[2]), "+f"(c[3])
                 : "r"(a[0]), "r"(a[1]), "r"(a[2]), "r"(a[3]), "r"(b[0]), "r"(b[1]));
}
__device__ __forceinline__ void red4(float* p, float a, float b, float c, float d) {
    asm volatile("red.global.add.v4.f32 [%0], {%1,%2,%3,%4};"
                 :: "l"(p), "f"(a), "f"(b), "f"(c), "f"(d) : "memory");
}
__device__ __forceinline__ uint2 pack_h4(float4 v) {
    __half2 p0 = __floats2half2_rn(v.x, v.y);
    __half2 p1 = __floats2half2_rn(v.z, v.w);
    uint2 u;
    u.x = *reinterpret_cast<uint32_t*>(&p0);
    u.y = *reinterpret_cast<uint32_t*>(&p1);
    return u;
}
__device__ __forceinline__ float gelu_x(float x) {
    return 0.5f * x * (1.0f + erff(x * 0.70710678118654752f));
}

// Precompute via fp16 MMA (same fragment addressing as score kernel):
// P[n][o] = nf[n] . W1[o][64*half .. +63], fp32 accum, fp16 store.
// 1536 warp-units = 256 node-tiles x {half a,b} x 3 col-chunks.
// Also zeroes out/denom and detects edge-index width.
__global__ __launch_bounds__(THREADS, 1) void precompute_kernel(
    const float* __restrict__ nf, const float* __restrict__ W1,
    const void* __restrict__ ei, float* __restrict__ out)
{
    extern __shared__ __align__(16) char sm[];
    uint32_t smb = (uint32_t)__cvta_generic_to_shared(sm);
    int tid = threadIdx.x, lane = tid & 31, wid = tid >> 5;

    // zero out + denom (grid-strided; 148*512 threads >= 65536 float4)
    {
        int gi = blockIdx.x * THREADS + tid;
        if (gi < NTOT * D / 4) ((float4*)out)[gi] = make_float4(0.f, 0.f, 0.f, 0.f);
        if (gi < NTOT) g_denom[gi] = 0.0f;
    }
    // int64 vs int32 detect (block 0; range-probe 512 int64 words)
    if (blockIdx.x == 0) {
        const long long* p = (const long long*)ei;
        long long v = p[tid];
        int ok = (v >= 0 && v < NTOT);
        int all = __syncthreads_and(ok);
        if (tid == 0) g_is64 = all;
    }

    // Stage both W halves as fp16 rows (o = output, 64 k, 144B rows)
    for (int i = tid; i < HDIM * 16; i += THREADS) {
        int o = i >> 4, r = i & 15;
        float4 va = *(const float4*)(W1 + o * HDIM + r * 4);
        float4 vb = *(const float4*)(W1 + o * HDIM + 64 + r * 4);
        *(uint2*)(sm + POFF_WA + o * ROWB + r * 8) = pack_h4(va);
        *(uint2*)(sm + POFF_WB + o * ROWB + r * 8) = pack_h4(vb);
    }
    __syncthreads();

    char* NF = sm + POFF_NF + wid * 2304;
    uint32_t nf_u = smb + POFF_NF + (uint32_t)(wid * 2304);

    const int NUNITS = (NTOT / 16) * 6;   // 1536
    for (int u = blockIdx.x * NWARP + wid; u < NUNITS; u += 148 * NWARP) {
        int tile = u / 6, sub = u - tile * 6;
        int half = sub >= 3;
        int nc = half ? sub - 3 : sub;
        __syncwarp();

        // gather 16 nf rows -> fp16 smem
        {
            int r = lane >> 1, h = lane & 1;
            const float4* rowp = (const float4*)(nf + (tile * 16 + r) * D);
            #pragma unroll
            for (int j = 0; j < 8; ++j) {
                float4 v = rowp[h * 8 + j];
                *(uint2*)(NF + r * ROWB + (h * 8 + j) * 8) = pack_h4(v);
            }
        }
        __syncwarp();

        uint32_t ahf[4][4];
        #pragma unroll
        for (int kk = 0; kk < 4; ++kk)
            ldsm4(ahf[kk], nf_u + (uint32_t)((lane & 15) * ROWB + kk * 32 + (lane >> 4) * 16));

        uint32_t wb_u = smb + (half ? POFF_WB : POFF_WA);
        int cb = nc * 64;
        float acc[8][4] = {};
        #pragma unroll
        for (int kk = 0; kk < 4; ++kk) {
            #pragma unroll
            for (int fp = 0; fp < 4; ++fp) {
                uint32_t wa = wb_u + (uint32_t)((cb + fp * 16 + (lane & 7) + ((lane >> 4) << 3)) * ROWB
                                                + kk * 32 + ((lane >> 3) & 1) * 16);
                uint32_t bh[4];
                ldsm4(bh, wa);
                mma_fp16(acc[2 * fp],     ahf[kk], bh);
                mma_fp16(acc[2 * fp + 1], ahf[kk], bh + 2);
            }
        }

        // store fp16 P (rows r0, r0+8; col pairs per f-group)
        __half* P = half ? g_PsH : g_PdH;
        int r0 = lane >> 2;
        int n0 = tile * 16 + r0;
        #pragma unroll
        for (int f = 0; f < 8; ++f) {
            int col = cb + f * 8 + 2 * (lane & 3);
            *(__half2*)(P + n0 * HDIM + col)       = __floats2half2_rn(acc[f][0], acc[f][1]);
            *(__half2*)(P + (n0 + 8) * HDIM + col) = __floats2half2_rn(acc[f][2], acc[f][3]);
        }
    }
}

// Warp-autonomous fused kernel: 16-edge warp tiles, single fp16 MMA, acc
// zero-init (P folded into the gelu epilogue to decouple L2 latency from
// the MMA chain). Exact fp32 edge rows kept in smem for output accumulate.
__global__ __launch_bounds__(THREADS, 1) void score_kernel(
    const float* __restrict__ adj, const float* __restrict__ W1,
    const float* __restrict__ W2, const void* __restrict__ ei,
    float* __restrict__ out, int E, int nwt)
{
    extern __shared__ __align__(16) char sm[];
    uint32_t smb = (uint32_t)__cvta_generic_to_shared(sm);
    float* W2s = (float*)(sm + OFF_W2);

    int tid = threadIdx.x, lane = tid & 31, wid = tid >> 5;
    int is64 = g_is64;

    // Stage W1c (cols 128..191) as fp16, rows = output o, K-major, 144B rows
    for (int i = tid; i < HDIM * 16; i += THREADS) {
        int o = i >> 4, r = i & 15;
        float4 v = *(const float4*)(W1 + o * HDIM + 128 + r * 4);
        *(uint2*)(sm + OFF_W + o * ROWB + r * 8) = pack_h4(v);
    }
    for (int i = tid; i < HDIM; i += THREADS) W2s[i] = W2[i];
    __syncthreads();

    char* Ah  = sm + OFF_A + wid * AWARP;       // fp16 rows [16][144]
    char* F32 = Ah + 2304;                      // fp32 rows [16][272]
    uint32_t ah_u = smb + OFF_A + wid * AWARP;
    uint32_t w_u  = smb + OFF_W;
    int*   sSw = (int*)(sm + OFF_SS) + wid * 16;
    int*   sDw = (int*)(sm + OFF_SD) + wid * 16;
    float* ATw = (float*)(sm + OFF_AT) + wid * 16;

    int gw = blockIdx.x * NWARP + wid;
    for (int wt = gw; wt < nwt; wt += gridDim.x * NWARP) {
        int tbase = wt * 16;
        // ---- stage indices ----
        if (lane < 16) {
            int ge = tbase + lane;
            int s = 0, d = 0;
            if (ge < E) {
                s = (int)ldidx(ei, ge, is64);
                d = (int)ldidx(ei, E + ge, is64);
            }
            sSw[lane] = s; sDw[lane] = d;
        }
        __syncwarp();
        // ---- gather adj rows: fp16 copy for MMA + fp32 copy for output ----
        {
            int r = lane >> 1, h = lane & 1;
            int ge = tbase + r;
            int s = sSw[r], d = sDw[r];
            const float4* rowp =
                (const float4*)(adj + ((long long)s * NNODES + (d & (NNODES - 1))) * D);
            #pragma unroll
            for (int j = 0; j < 8; ++j) {
                float4 v = (ge < E) ? rowp[h * 8 + j]
                                    : make_float4(0.f, 0.f, 0.f, 0.f);
                *(uint2*)(Ah + r * ROWB + (h * 8 + j) * 8) = pack_h4(v);
                *(float4*)(F32 + r * F32RB + (h * 8 + j) * 16) = v;
            }
        }
        __syncwarp();

        int r0 = lane >> 2, r1 = r0 + 8;
        int s0 = sSw[r0], d0 = sDw[r0], s1 = sSw[r1], d1 = sDw[r1];
        const __half2* pd0 = (const __half2*)(g_PdH + d0 * HDIM);
        const __half2* ps0 = (const __half2*)(g_PsH + s0 * HDIM);
        const __half2* pd1 = (const __half2*)(g_PdH + d1 * HDIM);
        const __half2* ps1 = (const __half2*)(g_PsH + s1 * HDIM);

        // A fragments are nc-invariant: hoist (4 kk x 4 regs)
        uint32_t ahf[4][4];
        #pragma unroll
        for (int kk = 0; kk < 4; ++kk) {
            uint32_t aoff = (uint32_t)((lane & 15) * ROWB + kk * 32 + (lane >> 4) * 16);
            ldsm4(ahf[kk], ah_u + aoff);
        }

        float z0 = 0.0f, z1 = 0.0f;
        #pragma unroll
        for (int nc = 0; nc < 3; ++nc) {
            float acc[8][4] = {};
            int cb = nc * 64;
            #pragma unroll
            for (int kk = 0; kk < 4; ++kk) {
                #pragma unroll
                for (int fp = 0; fp < 4; ++fp) {
                    // B frags for col groups f=2fp, 2fp+1 in one ldsm4
                    uint32_t wa = w_u + (uint32_t)((cb + fp * 16 + (lane & 7) + ((lane >> 4) << 3)) * ROWB
                                                   + kk * 32 + ((lane >> 3) & 1) * 16);
                    uint32_t bh[4];
                    ldsm4(bh, wa);
                    mma_fp16(acc[2 * fp],     ahf[kk], bh);
                    mma_fp16(acc[2 * fp + 1], ahf[kk], bh + 2);
                }
            }
            // epilogue: x = acc + Pd[dst] + Ps[src] (fp16 P), z += gelu(x)*W2
            #pragma unroll
            for (int f = 0; f < 8; ++f) {
                int c0 = cb + f * 8 + 2 * (lane & 3);   // even
                int ch = c0 >> 1;
                float2 a0 = __half22float2(pd0[ch]);
                float2 b0 = __half22float2(ps0[ch]);
                float2 a1 = __half22float2(pd1[ch]);
                float2 b1 = __half22float2(ps1[ch]);
                float2 w2v = *(const float2*)(W2s + c0);
                z0 = fmaf(gelu_x(acc[f][0] + a0.x + b0.x), w2v.x, z0);
                z0 = fmaf(gelu_x(acc[f][1] + a0.y + b0.y), w2v.y, z0);
                z1 = fmaf(gelu_x(acc[f][2] + a1.x + b1.x), w2v.x, z1);
                z1 = fmaf(gelu_x(acc[f][3] + a1.y + b1.y), w2v.y, z1);
            }
        }
        // quad reduce (lanes sharing the same rows)
        z0 += __shfl_xor_sync(0xffffffffu, z0, 1);
        z0 += __shfl_xor_sync(0xffffffffu, z0, 2);
        z1 += __shfl_xor_sync(0xffffffffu, z1, 1);
        z1 += __shfl_xor_sync(0xffffffffu, z1, 2);

        if ((lane & 3) == 0) {
            int df0 = (s0 > d0 ? s0 - d0 : d0 - s0);
            int df1 = (s1 > d1 ? s1 - d1 : d1 - s1);
            float at0 = (tbase + r0 < E && df0 > 1) ? expf(z0) : 0.0f;
            float at1 = (tbase + r1 < E && df1 > 1) ? expf(z1) : 0.0f;
            ATw[r0] = at0; ATw[r1] = at1;
            if (at0 != 0.0f) atomicAdd(&g_denom[d0], at0);
            if (at1 != 0.0f) atomicAdd(&g_denom[d1], at1);
        }
        __syncwarp();

        // weighted accumulate from the exact fp32 rows: 2 edges/pass, red.v4
        #pragma unroll
        for (int ep = 0; ep < 8; ++ep) {
            int e = 2 * ep + (lane >> 4);
            float a = ATw[e];
            if (a != 0.0f) {
                int c4 = lane & 15;
                float4 v = *(const float4*)(F32 + e * F32RB + c4 * 16);
                red4(out + sDw[e] * D + c4 * 4, v.x * a, v.y * a, v.z * a, v.w * a);
            }
        }
        __syncwarp();
    }
}

__global__ void finalize_kernel(float* __restrict__ out) {
    int i = blockIdx.x * blockDim.x + threadIdx.x;   // 65536 threads, float4 each
    float dn = g_denom[i >> 4];
    float inv = 1.0f / (dn == 0.0f ? 1.0f : dn);
    float4 v = ((float4*)out)[i];
    v.x *= inv; v.y *= inv; v.z *= inv; v.w *= inv;
    ((float4*)out)[i] = v;
}

extern "C" void kernel_launch(void* const* d_in, const int* in_sizes, int n_in,
                              void* d_out, int out_size) {
    const float* nf  = (const float*)d_in[0];
    const float* adj = (const float*)d_in[1];
    const float* W1  = (const float*)d_in[2];
    const float* W2  = (const float*)d_in[3];
    const void*  ei  = d_in[4];
    int E = in_sizes[4] / 2;
    if (E > EMAX) E = EMAX;

    cudaFuncSetAttribute(precompute_kernel, cudaFuncAttributeMaxDynamicSharedMemorySize, PSMEM_TOTAL);
    cudaFuncSetAttribute(score_kernel, cudaFuncAttributeMaxDynamicSharedMemorySize, SMEM_TOTAL);

    precompute_kernel<<<148, THREADS, PSMEM_TOTAL>>>(nf, W1, ei, (float*)d_out);

    int nwt = (E + 15) / 16;
    score_kernel<<<148, THREADS, SMEM_TOTAL>>>(adj, W1, W2, ei, (float*)d_out, E, nwt);

    finalize_kernel<<<256, 256>>>((float*)d_out);
}

// round 13
// speedup vs baseline: 1.7385x; 1.0437x over previous
#include <cuda_runtime.h>
#include <cuda_fp16.h>
#include <math.h>
#include <stdint.h>

#define D 64
#define NNODES 512
#define NTOT 4096
#define HDIM 192
#define EMAX 131072
#define NWARP 16
#define THREADS 512
#define NBLK 148
#define ROWB 144
#define F32RB 272

// ---- smem layout (bytes) ----
#define OFF_W   0                 // score W1c fp16 [192][72] rows = 27648
#define OFF_W2  27648             // 192 f32 = 768
#define OFF_A   28416             // phase1: WA+WB+NF (92160); phase2: 16 warps x 6912
#define AWARP   6912
#define OFF_SS  139008
#define OFF_SD  140032
#define OFF_AT  141056
#define SMEM_TOTAL 142080
// phase-1 aliases inside OFF_A region
#define P_WA (OFF_A)
#define P_WB (OFF_A + 27648)
#define P_NF (OFF_A + 55296)      // 16 warps x 2304 = 36864 (ends 120576 < 139008)

__device__ float    g_denom[NTOT];
__device__ __half   g_PdH[NTOT * HDIM];   // permuted fp16 P (dst half)
__device__ __half   g_PsH[NTOT * HDIM];   // permuted fp16 P (src half)
__device__ int      g_is64;
__device__ unsigned g_bcnt = 0;
__device__ unsigned g_bgen = 0;

__device__ __forceinline__ long long ldidx(const void* ei, int i, int is64) {
    return is64 ? ((const long long*)ei)[i] : (long long)((const int*)ei)[i];
}
__device__ __forceinline__ void ldsm4(uint32_t* r, uint32_t a) {
    asm volatile("ldmatrix.sync.aligned.m8n8.x4.shared.b16 {%0,%1,%2,%3}, [%4];"
                 : "=r"(r[0]), "=r"(r[1]), "=r"(r[2]), "=r"(r[3]) : "r"(a));
}
__device__ __forceinline__ void mma_fp16(float* c, const uint32_t* a, const uint32_t* b) {
    asm volatile("mma.sync.aligned.m16n8k16.row.col.f32.f16.f16.f32 "
                 "{%0,%1,%2,%3}, {%4,%5,%6,%7}, {%8,%9}, {%0,%1,%2,%3};"
                 : "+f"(c[0]), "+f"(c[1]), "+f"(c[2]), "+f"(c[3])
                 : "r"(a[0]), "r"(a[1]), "r"(a[2]), "r"(a[3]), "r"(b[0]), "r"(b[1]));
}
__device__ __forceinline__ void red4(float* p, float a, float b, float c, float d) {
    asm volatile("red.global.add.v4.f32 [%0], {%1,%2,%3,%4};"
                 :: "l"(p), "f"(a), "f"(b), "f"(c), "f"(d) : "memory");
}
__device__ __forceinline__ uint2 pack_h4(float4 v) {
    __half2 p0 = __floats2half2_rn(v.x, v.y);
    __half2 p1 = __floats2half2_rn(v.z, v.w);
    uint2 u;
    u.x = *reinterpret_cast<uint32_t*>(&p0);
    u.y = *reinterpret_cast<uint32_t*>(&p1);
    return u;
}
__device__ __forceinline__ float2 h2f(uint32_t u) {
    return __half22float2(*reinterpret_cast<__half2*>(&u));
}
__device__ __forceinline__ float gelu_x(float x) {
    return 0.5f * x * (1.0f + erff(x * 0.70710678118654752f));
}

// Sense-reversing software grid barrier. Safe: all NBLK blocks are resident
// (1 block/SM). Self-resetting across launches/graph replays.
__device__ __forceinline__ void grid_barrier() {
    __syncthreads();
    if (threadIdx.x == 0) {
        __threadfence();
        unsigned gen = *(volatile unsigned*)&g_bgen;
        unsigned old = atomicAdd(&g_bcnt, 1);
        if (old == NBLK - 1) {
            g_bcnt = 0;
            __threadfence();
            atomicAdd(&g_bgen, 1);
        } else {
            while (*(volatile unsigned*)&g_bgen == gen) __nanosleep(64);
        }
    }
    __syncthreads();
}

// One fused persistent kernel: zero/detect + P precompute (fp16 MMA) +
// grid barrier + edge scoring/accumulate + grid barrier + finalize.
__global__ __launch_bounds__(THREADS, 1) void fused_kernel(
    const float* __restrict__ nf, const float* __restrict__ adj,
    const float* __restrict__ W1, const float* __restrict__ W2,
    const void* __restrict__ ei, float* __restrict__ out, int E, int nwt)
{
    extern __shared__ __align__(16) char sm[];
    uint32_t smb = (uint32_t)__cvta_generic_to_shared(sm);
    float* W2s = (float*)(sm + OFF_W2);

    int tid = threadIdx.x, lane = tid & 31, wid = tid >> 5, qq = lane & 3;

    // ---- phase 0: zero out/denom, detect, stage all W tiles ----
    {
        int gi = blockIdx.x * THREADS + tid;
        if (gi < NTOT * D / 4) ((float4*)out)[gi] = make_float4(0.f, 0.f, 0.f, 0.f);
        if (gi < NTOT) g_denom[gi] = 0.0f;
    }
    if (blockIdx.x == 0) {
        const long long* p = (const long long*)ei;
        long long v = p[tid];
        int ok = (v >= 0 && v < NTOT);
        int all = __syncthreads_and(ok);
        if (tid == 0) g_is64 = all;
    }
    for (int i = tid; i < HDIM * 16; i += THREADS) {
        int o = i >> 4, r = i & 15;
        const float* wr = W1 + o * HDIM + r * 4;
        *(uint2*)(sm + P_WA  + o * ROWB + r * 8) = pack_h4(*(const float4*)(wr));
        *(uint2*)(sm + P_WB  + o * ROWB + r * 8) = pack_h4(*(const float4*)(wr + 64));
        *(uint2*)(sm + OFF_W + o * ROWB + r * 8) = pack_h4(*(const float4*)(wr + 128));
    }
    for (int i = tid; i < HDIM; i += THREADS) W2s[i] = W2[i];
    __syncthreads();

    // ---- phase 1: P precompute via fp16 MMA (permuted store layout) ----
    {
        char* NF = sm + P_NF + wid * 2304;
        uint32_t nf_u = smb + P_NF + (uint32_t)(wid * 2304);
        const int NUNITS = (NTOT / 16) * 6;   // 1536
        for (int u = blockIdx.x * NWARP + wid; u < NUNITS; u += NBLK * NWARP) {
            int tile = u / 6, sub = u - tile * 6;
            int half = sub >= 3;
            int nc = half ? sub - 3 : sub;
            __syncwarp();
            {
                int r = lane >> 1, h = lane & 1;
                const float4* rowp = (const float4*)(nf + (tile * 16 + r) * D);
                #pragma unroll
                for (int j = 0; j < 8; ++j)
                    *(uint2*)(NF + r * ROWB + (h * 8 + j) * 8) = pack_h4(rowp[h * 8 + j]);
            }
            __syncwarp();

            uint32_t ahf[4][4];
            #pragma unroll
            for (int kk = 0; kk < 4; ++kk)
                ldsm4(ahf[kk], nf_u + (uint32_t)((lane & 15) * ROWB + kk * 32 + (lane >> 4) * 16));

            uint32_t wb_u = smb + (half ? P_WB : P_WA);
            int cb = nc * 64;
            float acc[8][4] = {};
            #pragma unroll
            for (int kk = 0; kk < 4; ++kk) {
                #pragma unroll
                for (int fp = 0; fp < 4; ++fp) {
                    uint32_t wa = wb_u + (uint32_t)((cb + fp * 16 + (lane & 7) + ((lane >> 4) << 3)) * ROWB
                                                    + kk * 32 + ((lane >> 3) & 1) * 16);
                    uint32_t bh[4];
                    ldsm4(bh, wa);
                    mma_fp16(acc[2 * fp],     ahf[kk], bh);
                    mma_fp16(acc[2 * fp + 1], ahf[kk], bh + 2);
                }
            }
            // permuted store: pos = cb + (f>=4?32:0) + q*8 + (f&3)*2
            __half* P = half ? g_PsH : g_PdH;
            int n0 = tile * 16 + (lane >> 2);
            #pragma unroll
            for (int f = 0; f < 8; ++f) {
                int pos = cb + ((f & 4) << 3) + qq * 8 + (f & 3) * 2;
                *(__half2*)(P + n0 * HDIM + pos)       = __floats2half2_rn(acc[f][0], acc[f][1]);
                *(__half2*)(P + (n0 + 8) * HDIM + pos) = __floats2half2_rn(acc[f][2], acc[f][3]);
            }
        }
    }
    grid_barrier();

    // ---- phase 2: edge scoring + weighted accumulate ----
    {
        int is64 = *(volatile int*)&g_is64;
        char* Ah  = sm + OFF_A + wid * AWARP;       // fp16 rows [16][144]
        char* F32 = Ah + 2304;                      // fp32 rows [16][272]
        uint32_t ah_u = smb + OFF_A + wid * AWARP;
        uint32_t w_u  = smb + OFF_W;
        int*   sSw = (int*)(sm + OFF_SS) + wid * 16;
        int*   sDw = (int*)(sm + OFF_SD) + wid * 16;
        float* ATw = (float*)(sm + OFF_AT) + wid * 16;
        const char* PdB = (const char*)g_PdH;
        const char* PsB = (const char*)g_PsH;

        for (int wt = blockIdx.x * NWARP + wid; wt < nwt; wt += NBLK * NWARP) {
            int tbase = wt * 16;
            if (lane < 16) {
                int ge = tbase + lane;
                int s = 0, d = 0;
                if (ge < E) {
                    s = (int)ldidx(ei, ge, is64);
                    d = (int)ldidx(ei, E + ge, is64);
                }
                sSw[lane] = s; sDw[lane] = d;
            }
            __syncwarp();
            {
                int r = lane >> 1, h = lane & 1;
                int ge = tbase + r;
                int s = sSw[r], d = sDw[r];
                const float4* rowp =
                    (const float4*)(adj + ((long long)s * NNODES + (d & (NNODES - 1))) * D);
                #pragma unroll
                for (int j = 0; j < 8; ++j) {
                    float4 v = (ge < E) ? rowp[h * 8 + j]
                                        : make_float4(0.f, 0.f, 0.f, 0.f);
                    *(uint2*)(Ah + r * ROWB + (h * 8 + j) * 8) = pack_h4(v);
                    *(float4*)(F32 + r * F32RB + (h * 8 + j) * 16) = v;
                }
            }
            __syncwarp();

            int r0 = lane >> 2, r1 = r0 + 8;
            int s0 = sSw[r0], d0 = sDw[r0], s1 = sSw[r1], d1 = sDw[r1];
            const char* pd0 = PdB + d0 * 384;
            const char* ps0 = PsB + s0 * 384;
            const char* pd1 = PdB + d1 * 384;
            const char* ps1 = PsB + s1 * 384;

            uint32_t ahf[4][4];
            #pragma unroll
            for (int kk = 0; kk < 4; ++kk)
                ldsm4(ahf[kk], ah_u + (uint32_t)((lane & 15) * ROWB + kk * 32 + (lane >> 4) * 16));

            float z0 = 0.0f, z1 = 0.0f;
            #pragma unroll
            for (int nc = 0; nc < 3; ++nc) {
                float acc[8][4] = {};
                int cb = nc * 64;
                #pragma unroll
                for (int kk = 0; kk < 4; ++kk) {
                    #pragma unroll
                    for (int fp = 0; fp < 4; ++fp) {
                        uint32_t wa = w_u + (uint32_t)((cb + fp * 16 + (lane & 7) + ((lane >> 4) << 3)) * ROWB
                                                       + kk * 32 + ((lane >> 3) & 1) * 16);
                        uint32_t bh[4];
                        ldsm4(bh, wa);
                        mma_fp16(acc[2 * fp],     ahf[kk], bh);
                        mma_fp16(acc[2 * fp + 1], ahf[kk], bh + 2);
                    }
                }
                // epilogue: vectorized permuted-P loads (16B per pointer per phase)
                int ofs = nc * 128 + qq * 16;
                #pragma unroll
                for (int ph = 0; ph < 2; ++ph) {
                    uint4 A0 = *(const uint4*)(pd0 + ofs + ph * 64);
                    uint4 B0 = *(const uint4*)(ps0 + ofs + ph * 64);
                    uint4 A1 = *(const uint4*)(pd1 + ofs + ph * 64);
                    uint4 B1 = *(const uint4*)(ps1 + ofs + ph * 64);
                    const uint32_t* a0c = (const uint32_t*)&A0;
                    const uint32_t* b0c = (const uint32_t*)&B0;
                    const uint32_t* a1c = (const uint32_t*)&A1;
                    const uint32_t* b1c = (const uint32_t*)&B1;
                    #pragma unroll
                    for (int fj = 0; fj < 4; ++fj) {
                        int f = ph * 4 + fj;
                        float2 a0 = h2f(a0c[fj]), b0 = h2f(b0c[fj]);
                        float2 a1 = h2f(a1c[fj]), b1 = h2f(b1c[fj]);
                        int c0 = cb + f * 8 + 2 * qq;
                        float2 w2v = *(const float2*)(W2s + c0);
                        z0 = fmaf(gelu_x(acc[f][0] + a0.x + b0.x), w2v.x, z0);
                        z0 = fmaf(gelu_x(acc[f][1] + a0.y + b0.y), w2v.y, z0);
                        z1 = fmaf(gelu_x(acc[f][2] + a1.x + b1.x), w2v.x, z1);
                        z1 = fmaf(gelu_x(acc[f][3] + a1.y + b1.y), w2v.y, z1);
                    }
                }
            }
            z0 += __shfl_xor_sync(0xffffffffu, z0, 1);
            z0 += __shfl_xor_sync(0xffffffffu, z0, 2);
            z1 += __shfl_xor_sync(0xffffffffu, z1, 1);
            z1 += __shfl_xor_sync(0xffffffffu, z1, 2);

            if (qq == 0) {
                int df0 = (s0 > d0 ? s0 - d0 : d0 - s0);
                int df1 = (s1 > d1 ? s1 - d1 : d1 - s1);
                float at0 = (tbase + r0 < E && df0 > 1) ? expf(z0) : 0.0f;
                float at1 = (tbase + r1 < E && df1 > 1) ? expf(z1) : 0.0f;
                ATw[r0] = at0; ATw[r1] = at1;
                if (at0 != 0.0f) atomicAdd(&g_denom[d0], at0);
                if (at1 != 0.0f) atomicAdd(&g_denom[d1], at1);
            }
            __syncwarp();

            #pragma unroll
            for (int ep = 0; ep < 8; ++ep) {
                int e = 2 * ep + (lane >> 4);
                float a = ATw[e];
                if (a != 0.0f) {
                    int c4 = lane & 15;
                    float4 v = *(const float4*)(F32 + e * F32RB + c4 * 16);
                    red4(out + sDw[e] * D + c4 * 4, v.x * a, v.y * a, v.z * a, v.w * a);
                }
            }
            __syncwarp();
        }
    }
    grid_barrier();

    // ---- phase 3: finalize (divide by denom) ----
    {
        int gi = blockIdx.x * THREADS + tid;
        if (gi < NTOT * D / 4) {
            float dn = __ldcg(&g_denom[gi >> 4]);
            float inv = 1.0f / (dn == 0.0f ? 1.0f : dn);
            float4 v = __ldcg(((const float4*)out) + gi);
            v.x *= inv; v.y *= inv; v.z *= inv; v.w *= inv;
            ((float4*)out)[gi] = v;
        }
    }
}

extern "C" void kernel_launch(void* const* d_in, const int* in_sizes, int n_in,
                              void* d_out, int out_size) {
    const float* nf  = (const float*)d_in[0];
    const float* adj = (const float*)d_in[1];
    const float* W1  = (const float*)d_in[2];
    const float* W2  = (const float*)d_in[3];
    const void*  ei  = d_in[4];
    int E = in_sizes[4] / 2;
    if (E > EMAX) E = EMAX;

    cudaFuncSetAttribute(fused_kernel, cudaFuncAttributeMaxDynamicSharedMemorySize, SMEM_TOTAL);

    int nwt = (E + 15) / 16;
    fused_kernel<<<NBLK, THREADS, SMEM_TOTAL>>>(nf, adj, W1, W2, ei, (float*)d_out, E, nwt);
}

// round 14
// speedup vs baseline: 1.7565x; 1.0103x over previous
#include <cuda_runtime.h>
#include <cuda_fp16.h>
#include <math.h>
#include <stdint.h>

#define D 64
#define NNODES 512
#define NTOT 4096
#define HDIM 192
#define EMAX 131072
#define NWARP 16
#define THREADS 512
#define NBLK 148
#define ROWB 144
#define F32RB 272

// ---- smem layout (bytes) ----
#define OFF_W   0                 // score W1c fp16 [192][72] rows = 27648
#define OFF_W2  27648             // 192 f32 = 768
#define OFF_A   28416             // phase1: WA+WB+NF (92160); phase2: 16 warps x 6912
#define AWARP   6912
#define OFF_SS  139008
#define OFF_SD  140032
#define OFF_AT  141056
#define SMEM_TOTAL 142080
// phase-1 aliases inside OFF_A region
#define P_WA (OFF_A)
#define P_WB (OFF_A + 27648)
#define P_NF (OFF_A + 55296)

__device__ float    g_denom[NTOT];
__device__ __half   g_PdH[NTOT * HDIM];   // permuted fp16 P (dst half)
__device__ __half   g_PsH[NTOT * HDIM];   // permuted fp16 P (src half)
__device__ int      g_is64;
__device__ unsigned g_bcnt = 0;
__device__ unsigned g_bgen = 0;
__device__ unsigned g_wt   = 0;           // work-stealing ticket

__device__ __forceinline__ long long ldidx(const void* ei, int i, int is64) {
    return is64 ? ((const long long*)ei)[i] : (long long)((const int*)ei)[i];
}
__device__ __forceinline__ void ldsm4(uint32_t* r, uint32_t a) {
    asm volatile("ldmatrix.sync.aligned.m8n8.x4.shared.b16 {%0,%1,%2,%3}, [%4];"
                 : "=r"(r[0]), "=r"(r[1]), "=r"(r[2]), "=r"(r[3]) : "r"(a));
}
__device__ __forceinline__ void mma_fp16(float* c, const uint32_t* a, const uint32_t* b) {
    asm volatile("mma.sync.aligned.m16n8k16.row.col.f32.f16.f16.f32 "
                 "{%0,%1,%2,%3}, {%4,%5,%6,%7}, {%8,%9}, {%0,%1,%2,%3};"
                 : "+f"(c[0]), "+f"(c[1]), "+f"(c[2]), "+f"(c[3])
                 : "r"(a[0]), "r"(a[1]), "r"(a[2]), "r"(a[3]), "r"(b[0]), "r"(b[1]));
}
__device__ __forceinline__ void red4(float* p, float a, float b, float c, float d) {
    asm volatile("red.global.add.v4.f32 [%0], {%1,%2,%3,%4};"
                 :: "l"(p), "f"(a), "f"(b), "f"(c), "f"(d) : "memory");
}
__device__ __forceinline__ void pref_l1(const void* p) {
    asm volatile("prefetch.global.L1 [%0];" :: "l"(p));
}
__device__ __forceinline__ uint2 pack_h4(float4 v) {
    __half2 p0 = __floats2half2_rn(v.x, v.y);
    __half2 p1 = __floats2half2_rn(v.z, v.w);
    uint2 u;
    u.x = *reinterpret_cast<uint32_t*>(&p0);
    u.y = *reinterpret_cast<uint32_t*>(&p1);
    return u;
}
__device__ __forceinline__ float2 h2f(uint32_t u) {
    return __half22float2(*reinterpret_cast<__half2*>(&u));
}
__device__ __forceinline__ uint32_t hadd2u(uint32_t a, uint32_t b) {
    __half2 r = __hadd2(*reinterpret_cast<__half2*>(&a), *reinterpret_cast<__half2*>(&b));
    return *reinterpret_cast<uint32_t*>(&r);
}
__device__ __forceinline__ float gelu_x(float x) {
    return 0.5f * x * (1.0f + erff(x * 0.70710678118654752f));
}

// Sense-reversing software grid barrier (all NBLK blocks resident, 1/SM).
__device__ __forceinline__ void grid_barrier() {
    __syncthreads();
    if (threadIdx.x == 0) {
        __threadfence();
        unsigned gen = *(volatile unsigned*)&g_bgen;
        unsigned old = atomicAdd(&g_bcnt, 1);
        if (old == NBLK - 1) {
            g_bcnt = 0;
            __threadfence();
            atomicAdd(&g_bgen, 1);
        } else {
            while (*(volatile unsigned*)&g_bgen == gen) __nanosleep(64);
        }
    }
    __syncthreads();
}

__global__ __launch_bounds__(THREADS, 1) void fused_kernel(
    const float* __restrict__ nf, const float* __restrict__ adj,
    const float* __restrict__ W1, const float* __restrict__ W2,
    const void* __restrict__ ei, float* __restrict__ out, int E, int nwt)
{
    extern __shared__ __align__(16) char sm[];
    uint32_t smb = (uint32_t)__cvta_generic_to_shared(sm);
    float* W2s = (float*)(sm + OFF_W2);

    int tid = threadIdx.x, lane = tid & 31, wid = tid >> 5, qq = lane & 3;

    // ---- phase 0: zero out/denom, reset ticket, detect, stage W tiles ----
    {
        int gi = blockIdx.x * THREADS + tid;
        if (gi < NTOT * D / 4) ((float4*)out)[gi] = make_float4(0.f, 0.f, 0.f, 0.f);
        if (gi < NTOT) g_denom[gi] = 0.0f;
    }
    if (blockIdx.x == 0) {
        if (tid == 0) g_wt = 0;
        const long long* p = (const long long*)ei;
        long long v = p[tid];
        int ok = (v >= 0 && v < NTOT);
        int all = __syncthreads_and(ok);
        if (tid == 0) g_is64 = all;
    }
    for (int i = tid; i < HDIM * 16; i += THREADS) {
        int o = i >> 4, r = i & 15;
        const float* wr = W1 + o * HDIM + r * 4;
        *(uint2*)(sm + P_WA  + o * ROWB + r * 8) = pack_h4(*(const float4*)(wr));
        *(uint2*)(sm + P_WB  + o * ROWB + r * 8) = pack_h4(*(const float4*)(wr + 64));
        *(uint2*)(sm + OFF_W + o * ROWB + r * 8) = pack_h4(*(const float4*)(wr + 128));
    }
    for (int i = tid; i < HDIM; i += THREADS) W2s[i] = W2[i];
    __syncthreads();

    // ---- phase 1: P precompute via fp16 MMA (permuted store layout) ----
    {
        char* NF = sm + P_NF + wid * 2304;
        uint32_t nf_u = smb + P_NF + (uint32_t)(wid * 2304);
        const int NUNITS = (NTOT / 16) * 6;   // 1536
        for (int u = blockIdx.x * NWARP + wid; u < NUNITS; u += NBLK * NWARP) {
            int tile = u / 6, sub = u - tile * 6;
            int half = sub >= 3;
            int nc = half ? sub - 3 : sub;
            __syncwarp();
            {
                int r = lane >> 1, h = lane & 1;
                const float4* rowp = (const float4*)(nf + (tile * 16 + r) * D);
                #pragma unroll
                for (int j = 0; j < 8; ++j)
                    *(uint2*)(NF + r * ROWB + (h * 8 + j) * 8) = pack_h4(rowp[h * 8 + j]);
            }
            __syncwarp();

            uint32_t ahf[4][4];
            #pragma unroll
            for (int kk = 0; kk < 4; ++kk)
                ldsm4(ahf[kk], nf_u + (uint32_t)((lane & 15) * ROWB + kk * 32 + (lane >> 4) * 16));

            uint32_t wb_u = smb + (half ? P_WB : P_WA);
            int cb = nc * 64;
            float acc[8][4] = {};
            #pragma unroll
            for (int kk = 0; kk < 4; ++kk) {
                #pragma unroll
                for (int fp = 0; fp < 4; ++fp) {
                    uint32_t wa = wb_u + (uint32_t)((cb + fp * 16 + (lane & 7) + ((lane >> 4) << 3)) * ROWB
                                                    + kk * 32 + ((lane >> 3) & 1) * 16);
                    uint32_t bh[4];
                    ldsm4(bh, wa);
                    mma_fp16(acc[2 * fp],     ahf[kk], bh);
                    mma_fp16(acc[2 * fp + 1], ahf[kk], bh + 2);
                }
            }
            __half* P = half ? g_PsH : g_PdH;
            int n0 = tile * 16 + (lane >> 2);
            #pragma unroll
            for (int f = 0; f < 8; ++f) {
                int pos = cb + ((f & 4) << 3) + qq * 8 + (f & 3) * 2;
                *(__half2*)(P + n0 * HDIM + pos)       = __floats2half2_rn(acc[f][0], acc[f][1]);
                *(__half2*)(P + (n0 + 8) * HDIM + pos) = __floats2half2_rn(acc[f][2], acc[f][3]);
            }
        }
    }
    grid_barrier();

    // ---- phase 2: edge scoring + weighted accumulate (work-stealing) ----
    {
        int is64 = *(volatile int*)&g_is64;
        char* Ah  = sm + OFF_A + wid * AWARP;
        char* F32 = Ah + 2304;
        uint32_t ah_u = smb + OFF_A + wid * AWARP;
        uint32_t w_u  = smb + OFF_W;
        int*   sSw = (int*)(sm + OFF_SS) + wid * 16;
        int*   sDw = (int*)(sm + OFF_SD) + wid * 16;
        float* ATw = (float*)(sm + OFF_AT) + wid * 16;
        const char* PdB = (const char*)g_PdH;
        const char* PsB = (const char*)g_PsH;

        for (;;) {
            int wt;
            if (lane == 0) wt = (int)atomicAdd(&g_wt, 1u);
            wt = __shfl_sync(0xffffffffu, wt, 0);
            if (wt >= nwt) break;

            int tbase = wt * 16;
            if (lane < 16) {
                int ge = tbase + lane;
                int s = 0, d = 0;
                if (ge < E) {
                    s = (int)ldidx(ei, ge, is64);
                    d = (int)ldidx(ei, E + ge, is64);
                }
                sSw[lane] = s; sDw[lane] = d;
            }
            __syncwarp();

            int r0 = lane >> 2, r1 = r0 + 8;
            int s0 = sSw[r0], d0 = sDw[r0], s1 = sSw[r1], d1 = sDw[r1];
            const char* pd0 = PdB + d0 * 384;
            const char* ps0 = PsB + s0 * 384;
            const char* pd1 = PdB + d1 * 384;
            const char* ps1 = PsB + s1 * 384;
            // prefetch the 4 P rows (3 x 128B lines each) into L1
            if (qq < 3) {
                int po = qq * 128;
                pref_l1(pd0 + po); pref_l1(ps0 + po);
                pref_l1(pd1 + po); pref_l1(ps1 + po);
            }

            {
                int r = lane >> 1, h = lane & 1;
                int ge = tbase + r;
                int s = sSw[r], d = sDw[r];
                const float4* rowp =
                    (const float4*)(adj + ((long long)s * NNODES + (d & (NNODES - 1))) * D);
                #pragma unroll
                for (int j = 0; j < 8; ++j) {
                    float4 v = (ge < E) ? rowp[h * 8 + j]
                                        : make_float4(0.f, 0.f, 0.f, 0.f);
                    *(uint2*)(Ah + r * ROWB + (h * 8 + j) * 8) = pack_h4(v);
                    *(float4*)(F32 + r * F32RB + (h * 8 + j) * 16) = v;
                }
            }
            __syncwarp();

            uint32_t ahf[4][4];
            #pragma unroll
            for (int kk = 0; kk < 4; ++kk)
                ldsm4(ahf[kk], ah_u + (uint32_t)((lane & 15) * ROWB + kk * 32 + (lane >> 4) * 16));

            float z0 = 0.0f, z1 = 0.0f;
            #pragma unroll
            for (int nc = 0; nc < 3; ++nc) {
                float acc[8][4] = {};
                int cb = nc * 64;
                #pragma unroll
                for (int kk = 0; kk < 4; ++kk) {
                    #pragma unroll
                    for (int fp = 0; fp < 4; ++fp) {
                        uint32_t wa = w_u + (uint32_t)((cb + fp * 16 + (lane & 7) + ((lane >> 4) << 3)) * ROWB
                                                       + kk * 32 + ((lane >> 3) & 1) * 16);
                        uint32_t bh[4];
                        ldsm4(bh, wa);
                        mma_fp16(acc[2 * fp],     ahf[kk], bh);
                        mma_fp16(acc[2 * fp + 1], ahf[kk], bh + 2);
                    }
                }
                int ofs = nc * 128 + qq * 16;
                #pragma unroll
                for (int ph = 0; ph < 2; ++ph) {
                    uint4 A0 = *(const uint4*)(pd0 + ofs + ph * 64);
                    uint4 B0 = *(const uint4*)(ps0 + ofs + ph * 64);
                    uint4 A1 = *(const uint4*)(pd1 + ofs + ph * 64);
                    uint4 B1 = *(const uint4*)(ps1 + ofs + ph * 64);
                    const uint32_t* a0c = (const uint32_t*)&A0;
                    const uint32_t* b0c = (const uint32_t*)&B0;
                    const uint32_t* a1c = (const uint32_t*)&A1;
                    const uint32_t* b1c = (const uint32_t*)&B1;
                    #pragma unroll
                    for (int fj = 0; fj < 4; ++fj) {
                        int f = ph * 4 + fj;
                        float2 s0v = h2f(hadd2u(a0c[fj], b0c[fj]));
                        float2 s1v = h2f(hadd2u(a1c[fj], b1c[fj]));
                        int c0 = cb + f * 8 + 2 * qq;
                        float2 w2v = *(const float2*)(W2s + c0);
                        z0 = fmaf(gelu_x(acc[f][0] + s0v.x), w2v.x, z0);
                        z0 = fmaf(gelu_x(acc[f][1] + s0v.y), w2v.y, z0);
                        z1 = fmaf(gelu_x(acc[f][2] + s1v.x), w2v.x, z1);
                        z1 = fmaf(gelu_x(acc[f][3] + s1v.y), w2v.y, z1);
                    }
                }
            }
            z0 += __shfl_xor_sync(0xffffffffu, z0, 1);
            z0 += __shfl_xor_sync(0xffffffffu, z0, 2);
            z1 += __shfl_xor_sync(0xffffffffu, z1, 1);
            z1 += __shfl_xor_sync(0xffffffffu, z1, 2);

            if (qq == 0) {
                int df0 = (s0 > d0 ? s0 - d0 : d0 - s0);
                int df1 = (s1 > d1 ? s1 - d1 : d1 - s1);
                float at0 = (tbase + r0 < E && df0 > 1) ? expf(z0) : 0.0f;
                float at1 = (tbase + r1 < E && df1 > 1) ? expf(z1) : 0.0f;
                ATw[r0] = at0; ATw[r1] = at1;
                if (at0 != 0.0f) atomicAdd(&g_denom[d0], at0);
                if (at1 != 0.0f) atomicAdd(&g_denom[d1], at1);
            }
            __syncwarp();

            #pragma unroll
            for (int ep = 0; ep < 8; ++ep) {
                int e = 2 * ep + (lane >> 4);
                float a = ATw[e];
                if (a != 0.0f) {
                    int c4 = lane & 15;
                    float4 v = *(const float4*)(F32 + e * F32RB + c4 * 16);
                    red4(out + sDw[e] * D + c4 * 4, v.x * a, v.y * a, v.z * a, v.w * a);
                }
            }
            __syncwarp();
        }
    }
    grid_barrier();

    // ---- phase 3: finalize ----
    {
        int gi = blockIdx.x * THREADS + tid;
        if (gi < NTOT * D / 4) {
            float dn = __ldcg(&g_denom[gi >> 4]);
            float inv = 1.0f / (dn == 0.0f ? 1.0f : dn);
            float4 v = __ldcg(((const float4*)out) + gi);
            v.x *= inv; v.y *= inv; v.z *= inv; v.w *= inv;
            ((float4*)out)[gi] = v;
        }
    }
}

extern "C" void kernel_launch(void* const* d_in, const int* in_sizes, int n_in,
                              void* d_out, int out_size) {
    const float* nf  = (const float*)d_in[0];
    const float* adj = (const float*)d_in[1];
    const float* W1  = (const float*)d_in[2];
    const float* W2  = (const float*)d_in[3];
    const void*  ei  = d_in[4];
    int E = in_sizes[4] / 2;
    if (E > EMAX) E = EMAX;

    cudaFuncSetAttribute(fused_kernel, cudaFuncAttributeMaxDynamicSharedMemorySize, SMEM_TOTAL);

    int nwt = (E + 15) / 16;
    fused_kernel<<<NBLK, THREADS, SMEM_TOTAL>>>(nf, adj, W1, W2, ei, (float*)d_out, E, nwt);
}

// round 15
// speedup vs baseline: 1.7648x; 1.0047x over previous
#include <cuda_runtime.h>
#include <cuda_fp16.h>
#include <math.h>
#include <stdint.h>

#define D 64
#define NNODES 512
#define NTOT 4096
#define HDIM 192
#define EMAX 131072
#define NWARP 16
#define THREADS 512
#define NBLK 148
#define ROWB 144
#define F32RB 272

// ---- smem layout (bytes) ----
#define OFF_W   0                 // score W1c fp16 [192][72] rows = 27648
#define OFF_W2  27648             // 192 f32 = 768
#define OFF_A   28416             // phase1: WA+WB+NF (92160); phase2: 16 warps x 6912
#define AWARP   6912
#define OFF_SS  139008
#define OFF_SD  140032
#define OFF_AT  141056
#define SMEM_TOTAL 142080
// phase-1 aliases inside OFF_A region
#define P_WA (OFF_A)
#define P_WB (OFF_A + 27648)
#define P_NF (OFF_A + 55296)

__device__ float    g_denom[NTOT];
__device__ __half   g_PdH[NTOT * HDIM];   // permuted fp16 P (dst half)
__device__ __half   g_PsH[NTOT * HDIM];   // permuted fp16 P (src half)
__device__ int      g_is64;
__device__ unsigned g_bcnt = 0;
__device__ unsigned g_bgen = 0;
__device__ unsigned g_wt   = 0;           // work-stealing ticket

__device__ __forceinline__ long long ldidx(const void* ei, int i, int is64) {
    return is64 ? ((const long long*)ei)[i] : (long long)((const int*)ei)[i];
}
__device__ __forceinline__ void ldsm4(uint32_t* r, uint32_t a) {
    asm volatile("ldmatrix.sync.aligned.m8n8.x4.shared.b16 {%0,%1,%2,%3}, [%4];"
                 : "=r"(r[0]), "=r"(r[1]), "=r"(r[2]), "=r"(r[3]) : "r"(a));
}
__device__ __forceinline__ void mma_fp16(float* c, const uint32_t* a, const uint32_t* b) {
    asm volatile("mma.sync.aligned.m16n8k16.row.col.f32.f16.f16.f32 "
                 "{%0,%1,%2,%3}, {%4,%5,%6,%7}, {%8,%9}, {%0,%1,%2,%3};"
                 : "+f"(c[0]), "+f"(c[1]), "+f"(c[2]), "+f"(c[3])
                 : "r"(a[0]), "r"(a[1]), "r"(a[2]), "r"(a[3]), "r"(b[0]), "r"(b[1]));
}
__device__ __forceinline__ void red4(float* p, float a, float b, float c, float d) {
    asm volatile("red.global.add.v4.f32 [%0], {%1,%2,%3,%4};"
                 :: "l"(p), "f"(a), "f"(b), "f"(c), "f"(d) : "memory");
}
__device__ __forceinline__ void pref_l1(const void* p) {
    asm volatile("prefetch.global.L1 [%0];" :: "l"(p));
}
__device__ __forceinline__ uint2 pack_h4(float4 v) {
    __half2 p0 = __floats2half2_rn(v.x, v.y);
    __half2 p1 = __floats2half2_rn(v.z, v.w);
    uint2 u;
    u.x = *reinterpret_cast<uint32_t*>(&p0);
    u.y = *reinterpret_cast<uint32_t*>(&p1);
    return u;
}
__device__ __forceinline__ float2 h2f(uint32_t u) {
    return __half22float2(*reinterpret_cast<__half2*>(&u));
}
__device__ __forceinline__ uint32_t hadd2u(uint32_t a, uint32_t b) {
    __half2 r = __hadd2(*reinterpret_cast<__half2*>(&a), *reinterpret_cast<__half2*>(&b));
    return *reinterpret_cast<uint32_t*>(&r);
}
__device__ __forceinline__ float gelu_x(float x) {
    return 0.5f * x * (1.0f + erff(x * 0.70710678118654752f));
}

// Sense-reversing software grid barrier (all NBLK blocks resident, 1/SM).
__device__ __forceinline__ void grid_barrier() {
    __syncthreads();
    if (threadIdx.x == 0) {
        __threadfence();
        unsigned gen = *(volatile unsigned*)&g_bgen;
        unsigned old = atomicAdd(&g_bcnt, 1);
        if (old == NBLK - 1) {
            g_bcnt = 0;
            __threadfence();
            atomicAdd(&g_bgen, 1);
        } else {
            while (*(volatile unsigned*)&g_bgen == gen) __nanosleep(64);
        }
    }
    __syncthreads();
}

__global__ __launch_bounds__(THREADS, 1) void fused_kernel(
    const float* __restrict__ nf, const float* __restrict__ adj,
    const float* __restrict__ W1, const float* __restrict__ W2,
    const void* __restrict__ ei, float* __restrict__ out, int E, int nwt)
{
    extern __shared__ __align__(16) char sm[];
    uint32_t smb = (uint32_t)__cvta_generic_to_shared(sm);
    float* W2s = (float*)(sm + OFF_W2);

    int tid = threadIdx.x, lane = tid & 31, wid = tid >> 5, qq = lane & 3;

    // ---- phase 0: zero out/denom, reset ticket, detect, stage W tiles ----
    {
        int gi = blockIdx.x * THREADS + tid;
        if (gi < NTOT * D / 4) ((float4*)out)[gi] = make_float4(0.f, 0.f, 0.f, 0.f);
        if (gi < NTOT) g_denom[gi] = 0.0f;
    }
    if (blockIdx.x == 0) {
        if (tid == 0) g_wt = 0;
        const long long* p = (const long long*)ei;
        long long v = p[tid];
        int ok = (v >= 0 && v < NTOT);
        int all = __syncthreads_and(ok);
        if (tid == 0) g_is64 = all;
    }
    for (int i = tid; i < HDIM * 16; i += THREADS) {
        int o = i >> 4, r = i & 15;
        const float* wr = W1 + o * HDIM + r * 4;
        *(uint2*)(sm + P_WA  + o * ROWB + r * 8) = pack_h4(*(const float4*)(wr));
        *(uint2*)(sm + P_WB  + o * ROWB + r * 8) = pack_h4(*(const float4*)(wr + 64));
        *(uint2*)(sm + OFF_W + o * ROWB + r * 8) = pack_h4(*(const float4*)(wr + 128));
    }
    for (int i = tid; i < HDIM; i += THREADS) W2s[i] = W2[i];
    __syncthreads();

    // ---- phase 1: P precompute via fp16 MMA (permuted store layout) ----
    {
        char* NF = sm + P_NF + wid * 2304;
        uint32_t nf_u = smb + P_NF + (uint32_t)(wid * 2304);
        const int NUNITS = (NTOT / 16) * 6;   // 1536
        for (int u = blockIdx.x * NWARP + wid; u < NUNITS; u += NBLK * NWARP) {
            int tile = u / 6, sub = u - tile * 6;
            int half = sub >= 3;
            int nc = half ? sub - 3 : sub;
            __syncwarp();
            {
                int r = lane >> 1, h = lane & 1;
                const float4* rowp = (const float4*)(nf + (tile * 16 + r) * D);
                #pragma unroll
                for (int j = 0; j < 8; ++j)
                    *(uint2*)(NF + r * ROWB + (h * 8 + j) * 8) = pack_h4(rowp[h * 8 + j]);
            }
            __syncwarp();

            uint32_t ahf[4][4];
            #pragma unroll
            for (int kk = 0; kk < 4; ++kk)
                ldsm4(ahf[kk], nf_u + (uint32_t)((lane & 15) * ROWB + kk * 32 + (lane >> 4) * 16));

            uint32_t wb_u = smb + (half ? P_WB : P_WA);
            int cb = nc * 64;
            float acc[8][4] = {};
            #pragma unroll
            for (int kk = 0; kk < 4; ++kk) {
                #pragma unroll
                for (int fp = 0; fp < 4; ++fp) {
                    uint32_t wa = wb_u + (uint32_t)((cb + fp * 16 + (lane & 7) + ((lane >> 4) << 3)) * ROWB
                                                    + kk * 32 + ((lane >> 3) & 1) * 16);
                    uint32_t bh[4];
                    ldsm4(bh, wa);
                    mma_fp16(acc[2 * fp],     ahf[kk], bh);
                    mma_fp16(acc[2 * fp + 1], ahf[kk], bh + 2);
                }
            }
            __half* P = half ? g_PsH : g_PdH;
            int n0 = tile * 16 + (lane >> 2);
            #pragma unroll
            for (int f = 0; f < 8; ++f) {
                int pos = cb + ((f & 4) << 3) + qq * 8 + (f & 3) * 2;
                *(__half2*)(P + n0 * HDIM + pos)       = __floats2half2_rn(acc[f][0], acc[f][1]);
                *(__half2*)(P + (n0 + 8) * HDIM + pos) = __floats2half2_rn(acc[f][2], acc[f][3]);
            }
        }
    }
    grid_barrier();

    // ---- phase 2: edge scoring + weighted accumulate (work-stealing) ----
    {
        int is64 = *(volatile int*)&g_is64;
        char* Ah  = sm + OFF_A + wid * AWARP;
        char* F32 = Ah + 2304;
        uint32_t ah_u = smb + OFF_A + wid * AWARP;
        uint32_t w_u  = smb + OFF_W;
        int*   sSw = (int*)(sm + OFF_SS) + wid * 16;
        int*   sDw = (int*)(sm + OFF_SD) + wid * 16;
        float* ATw = (float*)(sm + OFF_AT) + wid * 16;
        const char* PdB = (const char*)g_PdH;
        const char* PsB = (const char*)g_PsH;

        for (;;) {
            int wt;
            if (lane == 0) wt = (int)atomicAdd(&g_wt, 1u);
            wt = __shfl_sync(0xffffffffu, wt, 0);
            if (wt >= nwt) break;

            int tbase = wt * 16;
            if (lane < 16) {
                int ge = tbase + lane;
                int s = 0, d = 0;
                if (ge < E) {
                    s = (int)ldidx(ei, ge, is64);
                    d = (int)ldidx(ei, E + ge, is64);
                }
                sSw[lane] = s; sDw[lane] = d;
            }
            __syncwarp();

            int r0 = lane >> 2, r1 = r0 + 8;
            int s0 = sSw[r0], d0 = sDw[r0], s1 = sSw[r1], d1 = sDw[r1];
            const char* pd0 = PdB + d0 * 384;
            const char* ps0 = PsB + s0 * 384;
            const char* pd1 = PdB + d1 * 384;
            const char* ps1 = PsB + s1 * 384;
            // prefetch the 4 P rows (3 x 128B lines each) into L1
            if (qq < 3) {
                int po = qq * 128;
                pref_l1(pd0 + po); pref_l1(ps0 + po);
                pref_l1(pd1 + po); pref_l1(ps1 + po);
            }

            {
                int r = lane >> 1, h = lane & 1;
                int ge = tbase + r;
                int s = sSw[r], d = sDw[r];
                const float4* rowp =
                    (const float4*)(adj + ((long long)s * NNODES + (d & (NNODES - 1))) * D);
                #pragma unroll
                for (int j = 0; j < 8; ++j) {
                    float4 v = (ge < E) ? rowp[h * 8 + j]
                                        : make_float4(0.f, 0.f, 0.f, 0.f);
                    *(uint2*)(Ah + r * ROWB + (h * 8 + j) * 8) = pack_h4(v);
                    *(float4*)(F32 + r * F32RB + (h * 8 + j) * 16) = v;
                }
            }
            __syncwarp();

            uint32_t ahf[4][4];
            #pragma unroll
            for (int kk = 0; kk < 4; ++kk)
                ldsm4(ahf[kk], ah_u + (uint32_t)((lane & 15) * ROWB + kk * 32 + (lane >> 4) * 16));

            float z0 = 0.0f, z1 = 0.0f;
            #pragma unroll
            for (int nc = 0; nc < 3; ++nc) {
                float acc[8][4] = {};
                int cb = nc * 64;
                #pragma unroll
                for (int kk = 0; kk < 4; ++kk) {
                    #pragma unroll
                    for (int fp = 0; fp < 4; ++fp) {
                        uint32_t wa = w_u + (uint32_t)((cb + fp * 16 + (lane & 7) + ((lane >> 4) << 3)) * ROWB
                                                       + kk * 32 + ((lane >> 3) & 1) * 16);
                        uint32_t bh[4];
                        ldsm4(bh, wa);
                        mma_fp16(acc[2 * fp],     ahf[kk], bh);
                        mma_fp16(acc[2 * fp + 1], ahf[kk], bh + 2);
                    }
                }
                int ofs = nc * 128 + qq * 16;
                #pragma unroll
                for (int ph = 0; ph < 2; ++ph) {
                    uint4 A0 = *(const uint4*)(pd0 + ofs + ph * 64);
                    uint4 B0 = *(const uint4*)(ps0 + ofs + ph * 64);
                    uint4 A1 = *(const uint4*)(pd1 + ofs + ph * 64);
                    uint4 B1 = *(const uint4*)(ps1 + ofs + ph * 64);
                    const uint32_t* a0c = (const uint32_t*)&A0;
                    const uint32_t* b0c = (const uint32_t*)&B0;
                    const uint32_t* a1c = (const uint32_t*)&A1;
                    const uint32_t* b1c = (const uint32_t*)&B1;
                    #pragma unroll
                    for (int fj = 0; fj < 4; ++fj) {
                        int f = ph * 4 + fj;
                        float2 s0v = h2f(hadd2u(a0c[fj], b0c[fj]));
                        float2 s1v = h2f(hadd2u(a1c[fj], b1c[fj]));
                        int c0 = cb + f * 8 + 2 * qq;
                        float2 w2v = *(const float2*)(W2s + c0);
                        z0 = fmaf(gelu_x(acc[f][0] + s0v.x), w2v.x, z0);
                        z0 = fmaf(gelu_x(acc[f][1] + s0v.y), w2v.y, z0);
                        z1 = fmaf(gelu_x(acc[f][2] + s1v.x), w2v.x, z1);
                        z1 = fmaf(gelu_x(acc[f][3] + s1v.y), w2v.y, z1);
                    }
                }
            }
            z0 += __shfl_xor_sync(0xffffffffu, z0, 1);
            z0 += __shfl_xor_sync(0xffffffffu, z0, 2);
            z1 += __shfl_xor_sync(0xffffffffu, z1, 1);
            z1 += __shfl_xor_sync(0xffffffffu, z1, 2);

            if (qq == 0) {
                int df0 = (s0 > d0 ? s0 - d0 : d0 - s0);
                int df1 = (s1 > d1 ? s1 - d1 : d1 - s1);
                float at0 = (tbase + r0 < E && df0 > 1) ? expf(z0) : 0.0f;
                float at1 = (tbase + r1 < E && df1 > 1) ? expf(z1) : 0.0f;
                ATw[r0] = at0; ATw[r1] = at1;
                if (at0 != 0.0f) atomicAdd(&g_denom[d0], at0);
                if (at1 != 0.0f) atomicAdd(&g_denom[d1], at1);
            }
            __syncwarp();

            #pragma unroll
            for (int ep = 0; ep < 8; ++ep) {
                int e = 2 * ep + (lane >> 4);
                float a = ATw[e];
                if (a != 0.0f) {
                    int c4 = lane & 15;
                    float4 v = *(const float4*)(F32 + e * F32RB + c4 * 16);
                    red4(out + sDw[e] * D + c4 * 4, v.x * a, v.y * a, v.z * a, v.w * a);
                }
            }
            __syncwarp();
        }
    }
    grid_barrier();

    // ---- phase 3: finalize ----
    {
        int gi = blockIdx.x * THREADS + tid;
        if (gi < NTOT * D / 4) {
            float dn = __ldcg(&g_denom[gi >> 4]);
            float inv = 1.0f / (dn == 0.0f ? 1.0f : dn);
            float4 v = __ldcg(((const float4*)out) + gi);
            v.x *= inv; v.y *= inv; v.z *= inv; v.w *= inv;
            ((float4*)out)[gi] = v;
        }
    }
}

extern "C" void kernel_launch(void* const* d_in, const int* in_sizes, int n_in,
                              void* d_out, int out_size) {
    const float* nf  = (const float*)d_in[0];
    const float* adj = (const float*)d_in[1];
    const float* W1  = (const float*)d_in[2];
    const float* W2  = (const float*)d_in[3];
    const void*  ei  = d_in[4];
    int E = in_sizes[4] / 2;
    if (E > EMAX) E = EMAX;

    cudaFuncSetAttribute(fused_kernel, cudaFuncAttributeMaxDynamicSharedMemorySize, SMEM_TOTAL);

    int nwt = (E + 15) / 16;
    fused_kernel<<<NBLK, THREADS, SMEM_TOTAL>>>(nf, adj, W1, W2, ei, (float*)d_out, E, nwt);
}